// round 2
// baseline (speedup 1.0000x reference)
#include <cuda_runtime.h>

#define DIM   128
#define NV    (DIM*DIM*DIM)      // 2097152
#define SLOPE 0.01f
#define BNEPS 1e-5f
#define MOFF  (16*NV)            // mask offset inside d_out

// ---------------- scratch (device globals: no allocs allowed) ----------------
__device__ float d_bufA[16*NV];
__device__ float d_bufB[16*NV];
__device__ float d_sum[5][16];
__device__ float d_sq[5][16];
__device__ float d_cnt;
__device__ float d_av[5][16];
__device__ float d_bv[5][16];

// ---------------- packed f32x2 helpers (Blackwell double-rate fp32) ----------
__device__ __forceinline__ unsigned long long pack2(float lo, float hi) {
    unsigned long long r;
    asm("mov.b64 %0, {%1, %2};" : "=l"(r) : "f"(lo), "f"(hi));
    return r;
}
__device__ __forceinline__ void unpack2(unsigned long long v, float& lo, float& hi) {
    asm("mov.b64 {%0, %1}, %2;" : "=f"(lo), "=f"(hi) : "l"(v));
}
__device__ __forceinline__ void fma2(unsigned long long& d, unsigned long long a,
                                     unsigned long long b) {
    asm("fma.rn.f32x2 %0, %1, %2, %0;" : "+l"(d) : "l"(a), "l"(b));
}

// ---------------- zero the per-launch stats ----------------------------------
__global__ void k_zero() {
    int t = threadIdx.x;
    if (t < 80) { (&d_sum[0][0])[t] = 0.f; (&d_sq[0][0])[t] = 0.f; }
    if (t == 0) d_cnt = 0.f;
}

// ---------------- layer 0: mask + 1x1 conv (4->16) + stats -------------------
__global__ __launch_bounds__(256) void k0(const float* __restrict__ feat,
                                          const int*   __restrict__ mask,
                                          const float* __restrict__ w0,
                                          const float* __restrict__ b0,
                                          float* __restrict__ out) {
    __shared__ float red[33];
    int tid = threadIdx.x;
    if (tid < 33) red[tid] = 0.f;
    __syncthreads();

    float wl[64];
#pragma unroll
    for (int i = 0; i < 64; i++) wl[i] = __ldg(w0 + i);
    float bl[16];
#pragma unroll
    for (int o = 0; o < 16; o++) bl[o] = __ldg(b0 + o);

    float s[16], q[16], cnt = 0.f;
#pragma unroll
    for (int o = 0; o < 16; o++) { s[o] = 0.f; q[o] = 0.f; }

    int stride = gridDim.x * blockDim.x;
    for (int p = blockIdx.x * blockDim.x + tid; p < NV; p += stride) {
        float m = (mask[p] > 0) ? 1.0f : 0.0f;
        out[MOFF + p] = m;
        cnt += m;
        float xa = feat[p];
        float xb = feat[NV   + p];
        float xc = feat[2*NV + p];
        float xd = feat[3*NV + p];
#pragma unroll
        for (int o = 0; o < 16; o++) {
            float yv = bl[o] + wl[o*4+0]*xa + wl[o*4+1]*xb
                             + wl[o*4+2]*xc + wl[o*4+3]*xd;
            yv *= m;
            d_bufA[o*NV + p] = yv;
            s[o] += yv;
            q[o] += yv * yv;
        }
    }

    // warp reduce 33 values
#pragma unroll
    for (int off = 16; off; off >>= 1) {
#pragma unroll
        for (int o = 0; o < 16; o++) {
            s[o] += __shfl_down_sync(0xffffffffu, s[o], off);
            q[o] += __shfl_down_sync(0xffffffffu, q[o], off);
        }
        cnt += __shfl_down_sync(0xffffffffu, cnt, off);
    }
    if ((tid & 31) == 0) {
#pragma unroll
        for (int o = 0; o < 16; o++) {
            atomicAdd(&red[o],      s[o]);
            atomicAdd(&red[16 + o], q[o]);
        }
        atomicAdd(&red[32], cnt);
    }
    __syncthreads();
    if (tid < 16) {
        atomicAdd(&d_sum[0][tid], red[tid]);
        atomicAdd(&d_sq[0][tid],  red[16 + tid]);
    }
    if (tid == 16) atomicAdd(&d_cnt, red[32]);
}

// ---------------- BN stats -> affine (a,b) -----------------------------------
__global__ void k_ab(int L, const float* __restrict__ g,
                     const float* __restrict__ be) {
    int c = threadIdx.x;
    if (c < 16) {
        float n    = d_cnt;
        float mean = d_sum[L][c] / n;
        float var  = d_sq[L][c] / n - mean * mean;
        float a    = __ldg(g + c) * rsqrtf(var + BNEPS);
        d_av[L][c] = a;
        d_bv[L][c] = __ldg(be + c) - mean * a;
    }
}

// ---------------- 3x3x3 conv (16->16), fused prev-BN/act on load -------------
#define SROW   132
#define SPLANE (6*SROW)

__global__ __launch_bounds__(512, 1) void k_conv(const float* __restrict__ w,
                                                 const float* __restrict__ bias,
                                                 const float* __restrict__ maskf,
                                                 int dir, int L, int AL) {
    __shared__ float sm[6*SPLANE];
    __shared__ float red[32];
    __shared__ float sa[16], sb[16];

    const float* x = dir ? d_bufB : d_bufA;
    float*       y = dir ? d_bufA : d_bufB;

    int tid = threadIdx.x;
    if (tid < 32) red[tid] = 0.f;
    if (tid >= 32 && tid < 48)  sa[tid - 32] = d_av[AL][tid - 32];
    if (tid >= 48 && tid < 64)  sb[tid - 48] = d_bv[AL][tid - 48];

    int osel = tid >> 8;          // 0: out ch 0..7, 1: out ch 8..15
    int col  = tid & 255;
    int x0   = (col & 15) * 8;    // 8 voxels along W
    int ly   = (col >> 4) & 3;
    int lz   = col >> 6;
    int y0   = blockIdx.y * 4;
    int z0   = blockIdx.z * 4;

    unsigned long long acc[8][4];
#pragma unroll
    for (int oo = 0; oo < 8; oo++)
#pragma unroll
        for (int v2 = 0; v2 < 4; v2++) acc[oo][v2] = 0ull;

    for (int c = 0; c < 16; c++) {
        __syncthreads();
        float ac = sa[c];
        float bc = sb[c];
        // stage channel c halo tile with fused affine + LeakyReLU + mask
        for (int i = tid; i < 6*6*130; i += 512) {
            int xx = i % 130;
            int r  = i / 130;
            int yy = r % 6;
            int zz = r / 6;
            int gx = xx - 1, gy = y0 + yy - 1, gz = z0 + zz - 1;
            float v = 0.f;
            if ((unsigned)gx < DIM && (unsigned)gy < DIM && (unsigned)gz < DIM) {
                int p   = (gz*DIM + gy)*DIM + gx;
                float t = x[c*NV + p];
                float m = maskf[p];
                float ss = ac * t + bc;
                v = m * fmaxf(ss, SLOPE * ss);
            }
            sm[zz*SPLANE + yy*SROW + xx] = v;
        }
        __syncthreads();

        for (int dz = 0; dz < 3; dz++) {
            for (int dy = 0; dy < 3; dy++) {
                const float* rp = &sm[(lz+dz)*SPLANE + (ly+dy)*SROW + x0];
                float xr[10];
#pragma unroll
                for (int j = 0; j < 10; j++) xr[j] = rp[j];
                unsigned long long px[3][4];
#pragma unroll
                for (int dx = 0; dx < 3; dx++)
#pragma unroll
                    for (int v2 = 0; v2 < 4; v2++)
                        px[dx][v2] = pack2(xr[2*v2+dx], xr[2*v2+dx+1]);

                const float* wp = w + ((osel*8)*16 + c)*27 + dz*9 + dy*3;
#pragma unroll
                for (int oo = 0; oo < 8; oo++) {
#pragma unroll
                    for (int dx = 0; dx < 3; dx++) {
                        float wv = __ldg(wp + oo*432 + dx);
                        unsigned long long pw = pack2(wv, wv);
#pragma unroll
                        for (int v2 = 0; v2 < 4; v2++)
                            fma2(acc[oo][v2], px[dx][v2], pw);
                    }
                }
            }
        }
    }

    // epilogue: bias, mask, store, stats
    int gz = z0 + lz, gy = y0 + ly;
    int pbase = (gz*DIM + gy)*DIM + x0;
    float mf[8];
#pragma unroll
    for (int j = 0; j < 8; j++) mf[j] = maskf[pbase + j];

    float ls[8], lq[8];
#pragma unroll
    for (int oo = 0; oo < 8; oo++) { ls[oo] = 0.f; lq[oo] = 0.f; }

#pragma unroll
    for (int oo = 0; oo < 8; oo++) {
        int o = osel*8 + oo;
        float bo = __ldg(bias + o);
#pragma unroll
        for (int v2 = 0; v2 < 4; v2++) {
            float lo, hi;
            unpack2(acc[oo][v2], lo, hi);
            float v0 = (lo + bo) * mf[2*v2];
            float v1 = (hi + bo) * mf[2*v2+1];
            *(float2*)(&y[o*NV + pbase + 2*v2]) = make_float2(v0, v1);
            ls[oo] += v0 + v1;
            lq[oo] += v0*v0 + v1*v1;
        }
    }

#pragma unroll
    for (int off = 16; off; off >>= 1) {
#pragma unroll
        for (int oo = 0; oo < 8; oo++) {
            ls[oo] += __shfl_down_sync(0xffffffffu, ls[oo], off);
            lq[oo] += __shfl_down_sync(0xffffffffu, lq[oo], off);
        }
    }
    if ((tid & 31) == 0) {
#pragma unroll
        for (int oo = 0; oo < 8; oo++) {
            atomicAdd(&red[osel*8 + oo],      ls[oo]);
            atomicAdd(&red[16 + osel*8 + oo], lq[oo]);
        }
    }
    __syncthreads();
    if (tid < 16) {
        atomicAdd(&d_sum[L][tid], red[tid]);
        atomicAdd(&d_sq[L][tid],  red[16 + tid]);
    }
}

// ---------------- layer 5: fused act + 1x1 conv (16->16) -> d_out ------------
__global__ __launch_bounds__(256) void k5(const float* __restrict__ w5,
                                          const float* __restrict__ b5,
                                          float* out) {
    __shared__ float ws[256];
    __shared__ float sa[16], sb[16], sbias[16];
    int tid = threadIdx.x;
    ws[tid] = __ldg(w5 + tid);
    if (tid < 16) {
        sa[tid]    = d_av[4][tid];
        sb[tid]    = d_bv[4][tid];
        sbias[tid] = __ldg(b5 + tid);
    }
    __syncthreads();

    int p4 = (blockIdx.x * blockDim.x + tid) * 4;
    if (p4 >= NV) return;

    float4 mfv = *(const float4*)(out + MOFF + p4);
    float mf[4] = {mfv.x, mfv.y, mfv.z, mfv.w};

    float acc[16][4];
#pragma unroll
    for (int o = 0; o < 16; o++)
#pragma unroll
        for (int j = 0; j < 4; j++) acc[o][j] = 0.f;

    for (int c = 0; c < 16; c++) {
        float a = sa[c], b = sb[c];
        float4 xv4 = *(const float4*)(d_bufA + c*NV + p4);
        float xv[4] = {xv4.x, xv4.y, xv4.z, xv4.w};
#pragma unroll
        for (int j = 0; j < 4; j++) {
            float s = a * xv[j] + b;
            xv[j] = mf[j] * fmaxf(s, SLOPE * s);
        }
#pragma unroll
        for (int o = 0; o < 16; o++) {
            float wv = ws[o*16 + c];
#pragma unroll
            for (int j = 0; j < 4; j++) acc[o][j] += wv * xv[j];
        }
    }
#pragma unroll
    for (int o = 0; o < 16; o++) {
        float bo = sbias[o];
        float4 r = make_float4((acc[o][0]+bo)*mf[0], (acc[o][1]+bo)*mf[1],
                               (acc[o][2]+bo)*mf[2], (acc[o][3]+bo)*mf[3]);
        *(float4*)(out + o*NV + p4) = r;
    }
}

// -----------------------------------------------------------------------------
extern "C" void kernel_launch(void* const* d_in, const int* in_sizes, int n_in,
                              void* d_out, int out_size) {
    const float* feat = (const float*)d_in[0];
    const int*   mask = (const int*)  d_in[1];
    const float* w0   = (const float*)d_in[2];
    const float* b0   = (const float*)d_in[3];
    const float* g0   = (const float*)d_in[4];
    const float* be0  = (const float*)d_in[5];
    float* out = (float*)d_out;
    const float* maskf = out + MOFF;

    k_zero<<<1, 128>>>();
    k0<<<1024, 256>>>(feat, mask, w0, b0, out);
    k_ab<<<1, 32>>>(0, g0, be0);

    dim3 cgrid(1, 32, 32);
    for (int l = 1; l <= 4; l++) {
        const float* w  = (const float*)d_in[2 + 4*l];
        const float* b  = (const float*)d_in[3 + 4*l];
        const float* g  = (const float*)d_in[4 + 4*l];
        const float* be = (const float*)d_in[5 + 4*l];
        int dir = (l - 1) & 1;          // l=1: A->B, l=2: B->A, ...
        k_conv<<<cgrid, 512>>>(w, b, maskf, dir, l, l - 1);
        k_ab<<<1, 32>>>(l, g, be);
    }
    // after 4 convs result is back in bufA
    const float* w5 = (const float*)d_in[22];
    const float* b5 = (const float*)d_in[23];
    k5<<<NV / 4 / 256, 256>>>(w5, b5, out);
}

// round 5
// speedup vs baseline: 1.0722x; 1.0722x over previous
#include <cuda_runtime.h>

#define DIM   128
#define NV    (DIM*DIM*DIM)      // 2097152
#define SLOPE 0.01f
#define BNEPS 1e-5f
#define MOFF  (16*NV)            // mask offset inside d_out

// ---------------- scratch (device globals: no allocs allowed) ----------------
__device__ float d_bufA[16*NV];          // raw conv outputs (and k0 output)
__device__ float d_bufB[16*NV];          // activated inputs for next conv
__device__ unsigned long long d_wp[4*16*9*2*24];   // packed dup weights, 4 layers
__device__ float d_sum[5][16];
__device__ float d_sq[5][16];
__device__ float d_cnt;
__device__ float d_av[5][16];
__device__ float d_bv[5][16];

// ---------------- packed f32x2 helpers (Blackwell double-rate fp32) ----------
__device__ __forceinline__ unsigned long long pack2(float lo, float hi) {
    unsigned long long r;
    asm("mov.b64 %0, {%1, %2};" : "=l"(r) : "f"(lo), "f"(hi));
    return r;
}
__device__ __forceinline__ void unpack2(unsigned long long v, float& lo, float& hi) {
    asm("mov.b64 {%0, %1}, %2;" : "=f"(lo), "=f"(hi) : "l"(v));
}
__device__ __forceinline__ void fma2(unsigned long long& d, unsigned long long a,
                                     unsigned long long b) {
    asm("fma.rn.f32x2 %0, %1, %2, %0;" : "+l"(d) : "l"(a), "l"(b));
}

// ---------------- zero the per-launch stats ----------------------------------
__global__ void k_zero() {
    int t = threadIdx.x;
    if (t < 80) { (&d_sum[0][0])[t] = 0.f; (&d_sq[0][0])[t] = 0.f; }
    if (t == 0) d_cnt = 0.f;
}

// ---------------- pack weights as (w,w) 64-bit pairs in inner-loop order -----
// flat idx = (((l*16 + c)*9 + t9)*2 + osel)*24 + (3*oo + dx)
__global__ void k_wprep(const float* __restrict__ w1, const float* __restrict__ w2,
                        const float* __restrict__ w3, const float* __restrict__ w4) {
    int i = blockIdx.x * blockDim.x + threadIdx.x;
    if (i >= 4*16*9*2*24) return;
    int t    = i % 24;  int r = i / 24;
    int osel = r & 1;   r >>= 1;
    int t9   = r % 9;   r /= 9;
    int c    = r & 15;
    int l    = r >> 4;                      // 0..3 -> layers 1..4
    const float* w = (l == 0) ? w1 : (l == 1) ? w2 : (l == 2) ? w3 : w4;
    int oo = t / 3, dx = t - 3*oo;
    int dz = t9 / 3, dy = t9 - 3*dz;
    int o  = osel*8 + oo;
    float v = w[(o*16 + c)*27 + dz*9 + dy*3 + dx];
    unsigned u = __float_as_uint(v);
    d_wp[i] = ((unsigned long long)u << 32) | (unsigned long long)u;
}

// ---------------- layer 0: mask + 1x1 conv (4->16) + stats -------------------
__global__ __launch_bounds__(256) void k0(const float* __restrict__ feat,
                                          const int*   __restrict__ mask,
                                          const float* __restrict__ w0,
                                          const float* __restrict__ b0,
                                          float* __restrict__ out) {
    __shared__ float red[33];
    int tid = threadIdx.x;
    if (tid < 33) red[tid] = 0.f;
    __syncthreads();

    float wl[64];
#pragma unroll
    for (int i = 0; i < 64; i++) wl[i] = __ldg(w0 + i);
    float bl[16];
#pragma unroll
    for (int o = 0; o < 16; o++) bl[o] = __ldg(b0 + o);

    float s[16], q[16], cnt = 0.f;
#pragma unroll
    for (int o = 0; o < 16; o++) { s[o] = 0.f; q[o] = 0.f; }

    int stride = gridDim.x * blockDim.x;
    for (int p = blockIdx.x * blockDim.x + tid; p < NV; p += stride) {
        float m = (mask[p] > 0) ? 1.0f : 0.0f;
        out[MOFF + p] = m;
        cnt += m;
        float xa = feat[p];
        float xb = feat[NV   + p];
        float xc = feat[2*NV + p];
        float xd = feat[3*NV + p];
#pragma unroll
        for (int o = 0; o < 16; o++) {
            float yv = bl[o] + wl[o*4+0]*xa + wl[o*4+1]*xb
                             + wl[o*4+2]*xc + wl[o*4+3]*xd;
            yv *= m;
            d_bufA[o*NV + p] = yv;
            s[o] += yv;
            q[o] += yv * yv;
        }
    }

#pragma unroll
    for (int off = 16; off; off >>= 1) {
#pragma unroll
        for (int o = 0; o < 16; o++) {
            s[o] += __shfl_down_sync(0xffffffffu, s[o], off);
            q[o] += __shfl_down_sync(0xffffffffu, q[o], off);
        }
        cnt += __shfl_down_sync(0xffffffffu, cnt, off);
    }
    if ((tid & 31) == 0) {
#pragma unroll
        for (int o = 0; o < 16; o++) {
            atomicAdd(&red[o],      s[o]);
            atomicAdd(&red[16 + o], q[o]);
        }
        atomicAdd(&red[32], cnt);
    }
    __syncthreads();
    if (tid < 16) {
        atomicAdd(&d_sum[0][tid], red[tid]);
        atomicAdd(&d_sq[0][tid],  red[16 + tid]);
    }
    if (tid == 16) atomicAdd(&d_cnt, red[32]);
}

// ---------------- BN stats -> affine (a,b) -----------------------------------
__global__ void k_ab(int L, const float* __restrict__ g,
                     const float* __restrict__ be) {
    int c = threadIdx.x;
    if (c < 16) {
        float n    = d_cnt;
        float mean = d_sum[L][c] / n;
        float var  = d_sq[L][c] / n - mean * mean;
        float a    = __ldg(g + c) * rsqrtf(var + BNEPS);
        d_av[L][c] = a;
        d_bv[L][c] = __ldg(be + c) - mean * a;
    }
}

// ---------------- activation pass: bufA (raw) -> bufB (BN+lrelu+mask) --------
__global__ __launch_bounds__(256) void k_act(const float* __restrict__ maskf, int L) {
    __shared__ float sa[16], sb[16];
    int tid = threadIdx.x;
    if (tid < 16)       sa[tid]      = d_av[L][tid];
    else if (tid < 32)  sb[tid - 16] = d_bv[L][tid - 16];
    __syncthreads();

    int p4 = (blockIdx.x * blockDim.x + tid) * 4;
    if (p4 >= NV) return;
    float4 m4 = *(const float4*)(maskf + p4);
    float mf[4] = {m4.x, m4.y, m4.z, m4.w};
#pragma unroll
    for (int c = 0; c < 16; c++) {
        float a = sa[c], b = sb[c];
        float4 r = *(const float4*)(d_bufA + c*NV + p4);
        float v[4] = {r.x, r.y, r.z, r.w};
#pragma unroll
        for (int j = 0; j < 4; j++) {
            float s = a * v[j] + b;
            v[j] = mf[j] * fmaxf(s, SLOPE * s);
        }
        *(float4*)(d_bufB + c*NV + p4) = make_float4(v[0], v[1], v[2], v[3]);
    }
}

// ---------------- 3x3x3 conv (16->16) on activated input ---------------------
#define SROW   132
#define SPLANE (6*SROW)     // 792
#define SBUF   (6*SPLANE)   // 4752

__global__ __launch_bounds__(512, 1) void k_conv(int l,
                                                 const float* __restrict__ bias,
                                                 const float* __restrict__ maskf) {
    __shared__ float sm[2*SBUF];
    __shared__ float red[32];

    const float* __restrict__ x = d_bufB;
    float*       __restrict__ y = d_bufA;
    const unsigned long long* __restrict__ wlay = d_wp + (l - 1) * (16*9*2*24);

    int tid  = threadIdx.x;
    int wid  = tid >> 5;
    int lane = tid & 31;
    if (tid < 32) red[tid] = 0.f;

    int osel = tid >> 8;          // 0: out ch 0..7, 1: out ch 8..15
    int col  = tid & 255;
    int x0   = (col & 15) * 8;    // 8 voxels along W
    int ly   = (col >> 4) & 3;
    int lz   = col >> 6;
    int y0   = blockIdx.y * 4;
    int z0   = blockIdx.z * 4;

    unsigned long long acc[8][4];
#pragma unroll
    for (int oo = 0; oo < 8; oo++)
#pragma unroll
        for (int v2 = 0; v2 < 4; v2++) acc[oo][v2] = 0ull;

    for (int c = 0; c < 16; c++) {
        float* sb = sm + (c & 1) * SBUF;
        // stage channel c halo tile (pure copy; zeros outside volume)
        for (int r = wid; r < 36; r += 16) {
            int zz = r / 6, yy = r - zz*6;
            int gy = y0 + yy - 1, gz = z0 + zz - 1;
            float* srow = sb + r * SROW;
            if ((unsigned)gy < DIM && (unsigned)gz < DIM) {
                const float* g = x + c*NV + (gz*DIM + gy)*DIM;
                float v0 = g[lane];
                float v1 = g[32 + lane];
                float v2 = g[64 + lane];
                float v3 = g[96 + lane];
                srow[1 + lane]  = v0;
                srow[33 + lane] = v1;
                srow[65 + lane] = v2;
                srow[97 + lane] = v3;
                if (lane == 0)  srow[0] = 0.f;
                if (lane >= 29) srow[100 + lane] = 0.f;   // 129,130,131
            } else {
                for (int i = lane; i < SROW; i += 32) srow[i] = 0.f;
            }
        }
        __syncthreads();

        const unsigned long long* wc = wlay + (c*9*2)*24 + osel*24;
#pragma unroll
        for (int dz = 0; dz < 3; dz++) {
#pragma unroll
            for (int dy = 0; dy < 3; dy++) {
                const float* rp = sb + (lz+dz)*SPLANE + (ly+dy)*SROW + x0;
                float4 A  = *(const float4*)rp;
                float4 B2 = *(const float4*)(rp + 4);
                float2 C2 = *(const float2*)(rp + 8);
                float xr[10] = {A.x, A.y, A.z, A.w, B2.x, B2.y, B2.z, B2.w,
                                C2.x, C2.y};
                unsigned long long px[3][4];
#pragma unroll
                for (int dx = 0; dx < 3; dx++)
#pragma unroll
                    for (int v2 = 0; v2 < 4; v2++)
                        px[dx][v2] = pack2(xr[2*v2 + dx], xr[2*v2 + dx + 1]);

                const unsigned long long* wt = wc + (dz*3 + dy)*48;
#pragma unroll
                for (int oo = 0; oo < 8; oo++) {
                    unsigned long long wv0 = __ldg(wt + 3*oo);
                    unsigned long long wv1 = __ldg(wt + 3*oo + 1);
                    unsigned long long wv2 = __ldg(wt + 3*oo + 2);
#pragma unroll
                    for (int v2 = 0; v2 < 4; v2++)
                        fma2(acc[oo][v2], px[0][v2], wv0);
#pragma unroll
                    for (int v2 = 0; v2 < 4; v2++)
                        fma2(acc[oo][v2], px[1][v2], wv1);
#pragma unroll
                    for (int v2 = 0; v2 < 4; v2++)
                        fma2(acc[oo][v2], px[2][v2], wv2);
                }
            }
        }
    }

    // epilogue: bias, mask, store raw, stats
    int gz = z0 + lz, gy = y0 + ly;
    int pbase = (gz*DIM + gy)*DIM + x0;
    float mf[8];
#pragma unroll
    for (int j = 0; j < 8; j++) mf[j] = maskf[pbase + j];

    float ls[8], lq[8];
#pragma unroll
    for (int oo = 0; oo < 8; oo++) { ls[oo] = 0.f; lq[oo] = 0.f; }

#pragma unroll
    for (int oo = 0; oo < 8; oo++) {
        int o = osel*8 + oo;
        float bo = __ldg(bias + o);
#pragma unroll
        for (int v2 = 0; v2 < 4; v2++) {
            float lo, hi;
            unpack2(acc[oo][v2], lo, hi);
            float v0 = (lo + bo) * mf[2*v2];
            float v1 = (hi + bo) * mf[2*v2+1];
            *(float2*)(&y[o*NV + pbase + 2*v2]) = make_float2(v0, v1);
            ls[oo] += v0 + v1;
            lq[oo] += v0*v0 + v1*v1;
        }
    }

#pragma unroll
    for (int off = 16; off; off >>= 1) {
#pragma unroll
        for (int oo = 0; oo < 8; oo++) {
            ls[oo] += __shfl_down_sync(0xffffffffu, ls[oo], off);
            lq[oo] += __shfl_down_sync(0xffffffffu, lq[oo], off);
        }
    }
    if ((tid & 31) == 0) {
#pragma unroll
        for (int oo = 0; oo < 8; oo++) {
            atomicAdd(&red[osel*8 + oo],      ls[oo]);
            atomicAdd(&red[16 + osel*8 + oo], lq[oo]);
        }
    }
    __syncthreads();
    if (tid < 16) {
        atomicAdd(&d_sum[l][tid], red[tid]);
        atomicAdd(&d_sq[l][tid],  red[16 + tid]);
    }
}

// ---------------- layer 5: fused act + 1x1 conv (16->16) -> d_out ------------
__global__ __launch_bounds__(256) void k5(const float* __restrict__ w5,
                                          const float* __restrict__ b5,
                                          float* out) {
    __shared__ float ws[256];
    __shared__ float sa[16], sb[16], sbias[16];
    int tid = threadIdx.x;
    ws[tid] = __ldg(w5 + tid);
    if (tid < 16) {
        sa[tid]    = d_av[4][tid];
        sb[tid]    = d_bv[4][tid];
        sbias[tid] = __ldg(b5 + tid);
    }
    __syncthreads();

    int p4 = (blockIdx.x * blockDim.x + tid) * 4;
    if (p4 >= NV) return;

    float4 mfv = *(const float4*)(out + MOFF + p4);
    float mf[4] = {mfv.x, mfv.y, mfv.z, mfv.w};

    float acc[16][4];
#pragma unroll
    for (int o = 0; o < 16; o++)
#pragma unroll
        for (int j = 0; j < 4; j++) acc[o][j] = 0.f;

#pragma unroll
    for (int c = 0; c < 16; c++) {
        float a = sa[c], b = sb[c];
        float4 xv4 = *(const float4*)(d_bufA + c*NV + p4);
        float xv[4] = {xv4.x, xv4.y, xv4.z, xv4.w};
#pragma unroll
        for (int j = 0; j < 4; j++) {
            float s = a * xv[j] + b;
            xv[j] = mf[j] * fmaxf(s, SLOPE * s);
        }
#pragma unroll
        for (int o = 0; o < 16; o++) {
            float wv = ws[o*16 + c];
#pragma unroll
            for (int j = 0; j < 4; j++) acc[o][j] += wv * xv[j];
        }
    }
#pragma unroll
    for (int o = 0; o < 16; o++) {
        float bo = sbias[o];
        float4 r = make_float4((acc[o][0]+bo)*mf[0], (acc[o][1]+bo)*mf[1],
                               (acc[o][2]+bo)*mf[2], (acc[o][3]+bo)*mf[3]);
        *(float4*)(out + o*NV + p4) = r;
    }
}

// -----------------------------------------------------------------------------
extern "C" void kernel_launch(void* const* d_in, const int* in_sizes, int n_in,
                              void* d_out, int out_size) {
    const float* feat = (const float*)d_in[0];
    const int*   mask = (const int*)  d_in[1];
    const float* w0   = (const float*)d_in[2];
    const float* b0   = (const float*)d_in[3];
    const float* g0   = (const float*)d_in[4];
    const float* be0  = (const float*)d_in[5];
    float* out = (float*)d_out;
    const float* maskf = out + MOFF;

    k_zero<<<1, 128>>>();
    k_wprep<<<108, 256>>>((const float*)d_in[6],  (const float*)d_in[10],
                          (const float*)d_in[14], (const float*)d_in[18]);
    k0<<<1024, 256>>>(feat, mask, w0, b0, out);
    k_ab<<<1, 32>>>(0, g0, be0);

    dim3 cgrid(1, 32, 32);
    for (int l = 1; l <= 4; l++) {
        const float* b  = (const float*)d_in[3 + 4*l];
        const float* g  = (const float*)d_in[4 + 4*l];
        const float* be = (const float*)d_in[5 + 4*l];
        k_act<<<NV/4/256, 256>>>(maskf, l - 1);
        k_conv<<<cgrid, 512>>>(l, b, maskf);
        k_ab<<<1, 32>>>(l, g, be);
    }
    const float* w5 = (const float*)d_in[22];
    const float* b5 = (const float*)d_in[23];
    k5<<<NV/4/256, 256>>>(w5, b5, out);
}